// round 6
// baseline (speedup 1.0000x reference)
#include <cuda_runtime.h>
#include <cuda_bf16.h>
#include <cstdint>

// ---------------- problem constants ----------------
#define NPOS   8192      // B*S positions
#define KCL    8192      // clusters
#define DDIM   1024      // feature dim
#define SBATCH 256       // S
#define NBATCH 32        // B
#define INV_T  (1.0f/0.07f)
#define INV_TP (1.0f/0.12f)

// ---------------- scratch (device globals; no allocation allowed) ----------------
__device__ __align__(256) __nv_bfloat16 g_Ah[NPOS*DDIM];
__device__ __align__(256) __nv_bfloat16 g_Al[NPOS*DDIM];
__device__ __align__(256) __nv_bfloat16 g_Bh[KCL*DDIM];
__device__ __align__(256) __nv_bfloat16 g_Bl[KCL*DDIM];
__device__ float g_mx[NBATCH*KCL];     // col max of logits/T
__device__ float g_u [NBATCH*KCL];     // column scalers
__device__ float g_v [NPOS];           // row scalers
__device__ float g_lse[NPOS];          // logsumexp(logits/0.12) per row
__device__ float g_rowloss[NPOS];

// ---------------- helpers ----------------
__device__ __forceinline__ uint32_t s2u(const void* p){
    uint32_t a;
    asm("{ .reg .u64 t; cvta.to.shared.u64 t, %1; cvt.u32.u64 %0, t; }":"=r"(a):"l"(p));
    return a;
}
__device__ __forceinline__ void cp16(uint32_t dst, const void* src){
    asm volatile("cp.async.cg.shared.global [%0], [%1], 16;" :: "r"(dst), "l"(src) : "memory");
}
__device__ __forceinline__ void cp_commit(){
    asm volatile("cp.async.commit_group;" ::: "memory");
}
template<int N> __device__ __forceinline__ void cp_wait(){
    asm volatile("cp.async.wait_group %0;" :: "n"(N) : "memory");
}
__device__ __forceinline__ void ldm_x4(uint32_t* r, uint32_t addr){
    asm volatile("ldmatrix.sync.aligned.m8n8.x4.shared.b16 {%0,%1,%2,%3}, [%4];"
                 : "=r"(r[0]), "=r"(r[1]), "=r"(r[2]), "=r"(r[3]) : "r"(addr));
}
__device__ __forceinline__ void ldm_x2(uint32_t* r, uint32_t addr){
    asm volatile("ldmatrix.sync.aligned.m8n8.x2.shared.b16 {%0,%1}, [%2];"
                 : "=r"(r[0]), "=r"(r[1]) : "r"(addr));
}
__device__ __forceinline__ void mma16816(float* c, const uint32_t* a, const uint32_t* b){
    asm volatile("mma.sync.aligned.m16n8k16.row.col.f32.bf16.bf16.f32 "
                 "{%0,%1,%2,%3}, {%4,%5,%6,%7}, {%8,%9}, {%0,%1,%2,%3};"
                 : "+f"(c[0]), "+f"(c[1]), "+f"(c[2]), "+f"(c[3])
                 : "r"(a[0]), "r"(a[1]), "r"(a[2]), "r"(a[3]), "r"(b[0]), "r"(b[1]));
}

// ---------------- prep: row-norm + A split (bf16 hi/lo) ----------------
__global__ void norm_splitA_kernel(const float* __restrict__ x){
    __shared__ float red[256];
    const int p = blockIdx.x, tid = threadIdx.x;
    const float* xr = x + (size_t)p * DDIM;
    float ss = 0.f;
    #pragma unroll
    for (int i = 0; i < 4; i++){ float v = xr[tid + i*256]; ss += v*v; }
    red[tid] = ss; __syncthreads();
    for (int o = 128; o > 0; o >>= 1){ if (tid < o) red[tid] += red[tid+o]; __syncthreads(); }
    float rn = 1.0f / fmaxf(sqrtf(red[0]), 1e-7f);
    #pragma unroll
    for (int i = 0; i < 4; i++){
        int d = tid + i*256;
        float v = xr[d] * rn;
        __nv_bfloat16 h = __float2bfloat16(v);
        g_Ah[(size_t)p*DDIM + d] = h;
        g_Al[(size_t)p*DDIM + d] = __float2bfloat16(v - __bfloat162float(h));
    }
}
__global__ void splitB_kernel(const float* __restrict__ W){
    size_t i = (size_t)blockIdx.x * 256 + threadIdx.x;
    float v = W[i];
    __nv_bfloat16 h = __float2bfloat16(v);
    g_Bh[i] = h;
    g_Bl[i] = __float2bfloat16(v - __bfloat162float(h));
}

// ---------------- GEMM: logits = A_n @ W^T via mma.sync bf16, 2-term split ----------------
// CTA tile 128x128, K-chunk 64 (128B smem rows + 16B-XOR swizzle), 2-stage cp.async pipeline.
// 8 warps in 2(M) x 4(N) grid; warp tile 64x32; 3 mma per (mi,ni,k16) for the split terms.
#define GEMM_SMEM (2*65536)   // 2 stages * 4 tiles * 16KB

// issue cp.async for one stage: 4 tiles (Ah,Al,Bh,Bl), each 128 rows x 64 bf16
__device__ __forceinline__ void load_stage(uint32_t sm_stage,
                                           const __nv_bfloat16* const* gsrc,
                                           int ckk, int tid){
    #pragma unroll
    for (int t = 0; t < 4; t++){
        const char* src = (const char*)(gsrc[t] + ckk * 64);
        uint32_t dT = sm_stage + t * 16384;
        #pragma unroll
        for (int i = 0; i < 4; i++){
            int q = i * 256 + tid;        // 0..1023 : 16B chunk id
            int r = q >> 3, c = q & 7;
            const void* s = src + (size_t)r * (DDIM*2) + c * 16;
            uint32_t d = dT + (uint32_t)(r * 128) + (uint32_t)((c ^ (r & 7)) << 4);
            cp16(d, s);
        }
    }
    cp_commit();
}

__global__ void __launch_bounds__(256, 1) gemm_kernel(float* __restrict__ C){
    extern __shared__ char smem[];
    const uint32_t sb = s2u(smem);
    const int tid = threadIdx.x;
    const int wid = tid >> 5, lane = tid & 31;
    const int wm = wid >> 2;            // 0..1
    const int wn = wid & 3;             // 0..3
    const int m0 = blockIdx.y * 128;
    const int n0 = blockIdx.x * 128;

    const __nv_bfloat16* gsrc[4] = {
        g_Ah + (size_t)m0 * DDIM, g_Al + (size_t)m0 * DDIM,
        g_Bh + (size_t)n0 * DDIM, g_Bl + (size_t)n0 * DDIM };

    float acc[4][4][4];
    #pragma unroll
    for (int a = 0; a < 4; a++)
        #pragma unroll
        for (int b = 0; b < 4; b++)
            #pragma unroll
            for (int c = 0; c < 4; c++) acc[a][b][c] = 0.f;

    // precomputed ldmatrix lane addressing (within-tile, before stage base)
    const int aRow = wm * 64 + (lane & 15);          // + mi*16
    const int aHalf = lane >> 4;                     // 0/1 -> +16B chunk
    const int l15 = lane & 15;
    const int bRow = wn * 32 + (l15 & 7);            // + ni*8
    const int bHalf = (l15 >> 3) & 1;

    load_stage(sb,         gsrc, 0, tid);
    load_stage(sb + 65536, gsrc, 1, tid);

    for (int ck = 0; ck < 16; ck++){
        if (ck == 15) cp_wait<0>(); else cp_wait<1>();
        __syncthreads();

        const uint32_t stage = sb + (uint32_t)((ck & 1) * 65536);
        const uint32_t sAh = stage, sAl = stage + 16384;
        const uint32_t sBh = stage + 32768, sBl = stage + 49152;

        #pragma unroll
        for (int kk = 0; kk < 4; kk++){
            uint32_t Ah4[4][4], Al4[4][4], Bh2[4][2], Bl2[4][2];
            #pragma unroll
            for (int mi = 0; mi < 4; mi++){
                int row = aRow + mi * 16;
                int ch  = kk * 2 + aHalf;
                uint32_t off = (uint32_t)(row * 128 + ((ch ^ (row & 7)) << 4));
                ldm_x4(Ah4[mi], sAh + off);
                ldm_x4(Al4[mi], sAl + off);
            }
            #pragma unroll
            for (int ni = 0; ni < 4; ni++){
                int row = bRow + ni * 8;
                int ch  = kk * 2 + bHalf;
                uint32_t off = (uint32_t)(row * 128 + ((ch ^ (row & 7)) << 4));
                ldm_x2(Bh2[ni], sBh + off);
                ldm_x2(Bl2[ni], sBl + off);
            }
            #pragma unroll
            for (int mi = 0; mi < 4; mi++)
                #pragma unroll
                for (int ni = 0; ni < 4; ni++){
                    mma16816(acc[mi][ni], Ah4[mi], Bh2[ni]);
                    mma16816(acc[mi][ni], Ah4[mi], Bl2[ni]);
                    mma16816(acc[mi][ni], Al4[mi], Bh2[ni]);
                }
        }
        __syncthreads();                 // all warps done reading this buffer
        if (ck + 2 < 16)
            load_stage(sb + (uint32_t)((ck & 1) * 65536), gsrc, ck + 2, tid);
    }

    // epilogue: write fp32 logits
    float* Cp = C + (size_t)(m0 + wm * 64) * KCL + n0 + wn * 32;
    const int rr = lane >> 2, cc = (lane & 3) * 2;
    #pragma unroll
    for (int mi = 0; mi < 4; mi++)
        #pragma unroll
        for (int ni = 0; ni < 4; ni++){
            float* p0 = Cp + (size_t)(mi * 16 + rr) * KCL + ni * 8 + cc;
            float* p1 = p0 + (size_t)8 * KCL;
            *reinterpret_cast<float2*>(p0) = make_float2(acc[mi][ni][0], acc[mi][ni][1]);
            *reinterpret_cast<float2*>(p1) = make_float2(acc[mi][ni][2], acc[mi][ni][3]);
        }
}

// ---------------- Sinkhorn passes (logits live in d_out, E recomputed on the fly) ----------------
// col0: per (b,k): mx = max_s logits/T ; u = 1/(sum_s exp(l/T - mx + 50) + eps)
__global__ void col0_kernel(const float* __restrict__ L){
    int g = blockIdx.x * 256 + threadIdx.x;           // 0 .. 32*8192-1
    int b = g >> 13, k = g & (KCL - 1);
    const float* p = L + (size_t)b * SBATCH * KCL + k;
    float m = -3.4e38f;
    #pragma unroll 8
    for (int s = 0; s < SBATCH; s++) m = fmaxf(m, p[(size_t)s * KCL] * INV_T);
    float sum = 0.f;
    #pragma unroll 8
    for (int s = 0; s < SBATCH; s++) sum += expf(p[(size_t)s * KCL] * INV_T - m + 50.0f);
    g_mx[g] = m;
    g_u[g]  = 1.0f / (sum + 1e-8f);
}
// weighted col pass: c = u*sum_s E*v[s]; u <- u/(c+eps)
__global__ void colw_kernel(const float* __restrict__ L){
    int g = blockIdx.x * 256 + threadIdx.x;
    int b = g >> 13, k = g & (KCL - 1);
    const float* p = L + (size_t)b * SBATCH * KCL + k;
    const float* vv = g_v + b * SBATCH;
    float mxv = g_mx[g];
    float t = 0.f;
    #pragma unroll 8
    for (int s = 0; s < SBATCH; s++)
        t += expf(p[(size_t)s * KCL] * INV_T - mxv + 50.0f) * vv[s];
    float uo = g_u[g];
    g_u[g] = uo / (uo * t + 1e-8f);
}
// row pass: r = v*sum_k E*u[k]; v <- v/(r+eps). First call also computes lse(logits/0.12).
__global__ void row_kernel(const float* __restrict__ L, int first, int computeLse){
    const int p = blockIdx.x, tid = threadIdx.x;
    const int b = p >> 8;
    const float* row = L + (size_t)p * KCL;
    const float* mx = g_mx + (size_t)b * KCL;
    const float* uu = g_u  + (size_t)b * KCL;
    float t = 0.f, pm = -3.4e38f, ps = 0.f;
    for (int k = tid; k < KCL; k += 256){
        float l = row[k];
        t += expf(l * INV_T - mx[k] + 50.0f) * uu[k];
        if (computeLse){
            float q = l * INV_TP;
            float nm = fmaxf(pm, q);
            ps = ps * expf(pm - nm) + expf(q - nm);
            pm = nm;
        }
    }
    __shared__ float st[256], sm[256], ss[256];
    st[tid] = t; sm[tid] = pm; ss[tid] = ps; __syncthreads();
    for (int o = 128; o > 0; o >>= 1){
        if (tid < o){
            st[tid] += st[tid + o];
            float m1 = sm[tid], m2 = sm[tid + o];
            float nm = fmaxf(m1, m2);
            ss[tid] = ss[tid] * expf(m1 - nm) + ss[tid + o] * expf(m2 - nm);
            sm[tid] = nm;
        }
        __syncthreads();
    }
    if (tid == 0){
        float vo = first ? 1.0f : g_v[p];
        g_v[p] = vo / (vo * st[0] + 1e-8f);
        if (computeLse) g_lse[p] = sm[0] + logf(ss[0]);
    }
}
// final: assignments in place + per-row loss partial (deterministic)
__global__ void final_kernel(float* __restrict__ L){
    const int p = blockIdx.x, tid = threadIdx.x;
    const int b = p >> 8;
    float v = g_v[p], lse = g_lse[p];
    float* row = L + (size_t)p * KCL;
    const float* mx = g_mx + (size_t)b * KCL;
    const float* uu = g_u  + (size_t)b * KCL;
    float acc = 0.f;
    for (int k = tid; k < KCL; k += 256){
        float l = row[k];
        float a = expf(l * INV_T - mx[k] + 50.0f) * uu[k] * v;
        row[k] = a;
        acc += a * (l * INV_TP - lse);
    }
    __shared__ float red[256];
    red[tid] = acc; __syncthreads();
    for (int o = 128; o > 0; o >>= 1){ if (tid < o) red[tid] += red[tid+o]; __syncthreads(); }
    if (tid == 0) g_rowloss[p] = red[0];
}
__global__ void loss_kernel(float* __restrict__ out, int idx){
    __shared__ float red[256];
    const int tid = threadIdx.x;
    float s = 0.f;
    for (int i = tid; i < NPOS; i += 256) s += g_rowloss[i];
    red[tid] = s; __syncthreads();
    for (int o = 128; o > 0; o >>= 1){ if (tid < o) red[tid] += red[tid+o]; __syncthreads(); }
    if (tid == 0) out[idx] = -red[0] * (1.0f / (float)NPOS);
}

// ---------------- launch ----------------
extern "C" void kernel_launch(void* const* d_in, const int* in_sizes, int n_in,
                              void* d_out, int out_size){
    (void)in_sizes; (void)n_in;
    const float* x = (const float*)d_in[0];   // [32,256,1024]
    const float* W = (const float*)d_in[1];   // [8192,1024]
    float* out = (float*)d_out;               // assignments [8192,8192] (+ loss at end)

    static int attr_done = 0;
    if (!attr_done){
        cudaFuncSetAttribute(gemm_kernel, cudaFuncAttributeMaxDynamicSharedMemorySize, GEMM_SMEM);
        attr_done = 1;
    }

    norm_splitA_kernel<<<NPOS, 256>>>(x);
    splitB_kernel<<<(KCL * DDIM) / 256, 256>>>(W);
    gemm_kernel<<<dim3(KCL / 128, NPOS / 128), 256, GEMM_SMEM>>>(out);

    const int colBlocks = (NBATCH * KCL) / 256;   // 1024
    col0_kernel<<<colBlocks, 256>>>(out);         // iter1 col (+ colmax)
    row_kernel <<<NPOS, 256>>>(out, 1, 1);        // iter1 row (+ lse for loss)
    colw_kernel<<<colBlocks, 256>>>(out);         // iter2 col
    row_kernel <<<NPOS, 256>>>(out, 0, 0);        // iter2 row
    colw_kernel<<<colBlocks, 256>>>(out);         // iter3 col
    row_kernel <<<NPOS, 256>>>(out, 0, 0);        // iter3 row
    final_kernel<<<NPOS, 256>>>(out);             // assignments + row loss

    if (out_size > NPOS * KCL)
        loss_kernel<<<1, 256>>>(out, out_size - 1);
}

// round 7
// speedup vs baseline: 1.1582x; 1.1582x over previous
#include <cuda_runtime.h>
#include <cuda_bf16.h>
#include <cstdint>

// ---------------- problem constants ----------------
#define NPOS   8192      // B*S positions
#define KCL    8192      // clusters
#define DDIM   1024      // feature dim
#define SBATCH 256       // S
#define NBATCH 32        // B
#define INV_T  (1.0f/0.07f)
#define INV_TP (1.0f/0.12f)
#define SHIFT  30.0f     // constant exp shift (column-constant => cancels in Sinkhorn)

// ---------------- scratch (device globals; no allocation allowed) ----------------
__device__ __align__(256) __nv_bfloat16 g_Ah[NPOS*DDIM];
__device__ __align__(256) __nv_bfloat16 g_Al[NPOS*DDIM];
__device__ __align__(256) __nv_bfloat16 g_Bh[KCL*DDIM];
__device__ __align__(256) __nv_bfloat16 g_Bl[KCL*DDIM];
__device__ float g_cs[NBATCH*KCL];     // column sums (from GEMM epilogue)
__device__ float g_u [NBATCH*KCL];     // column scalers
__device__ float g_v [NPOS];           // row scalers
__device__ float g_lse[NPOS];          // logsumexp(logits/0.12) per row
__device__ float g_rowloss[NPOS];

// ---------------- helpers ----------------
__device__ __forceinline__ uint32_t s2u(const void* p){
    uint32_t a;
    asm("{ .reg .u64 t; cvta.to.shared.u64 t, %1; cvt.u32.u64 %0, t; }":"=r"(a):"l"(p));
    return a;
}
__device__ __forceinline__ void cp16(uint32_t dst, const void* src){
    asm volatile("cp.async.cg.shared.global [%0], [%1], 16;" :: "r"(dst), "l"(src) : "memory");
}
__device__ __forceinline__ void cp_commit(){
    asm volatile("cp.async.commit_group;" ::: "memory");
}
template<int N> __device__ __forceinline__ void cp_wait(){
    asm volatile("cp.async.wait_group %0;" :: "n"(N) : "memory");
}
__device__ __forceinline__ void ldm_x4(uint32_t* r, uint32_t addr){
    asm volatile("ldmatrix.sync.aligned.m8n8.x4.shared.b16 {%0,%1,%2,%3}, [%4];"
                 : "=r"(r[0]), "=r"(r[1]), "=r"(r[2]), "=r"(r[3]) : "r"(addr));
}
__device__ __forceinline__ void ldm_x2(uint32_t* r, uint32_t addr){
    asm volatile("ldmatrix.sync.aligned.m8n8.x2.shared.b16 {%0,%1}, [%2];"
                 : "=r"(r[0]), "=r"(r[1]) : "r"(addr));
}
__device__ __forceinline__ void mma16816(float* c, const uint32_t* a, const uint32_t* b){
    asm volatile("mma.sync.aligned.m16n8k16.row.col.f32.bf16.bf16.f32 "
                 "{%0,%1,%2,%3}, {%4,%5,%6,%7}, {%8,%9}, {%0,%1,%2,%3};"
                 : "+f"(c[0]), "+f"(c[1]), "+f"(c[2]), "+f"(c[3])
                 : "r"(a[0]), "r"(a[1]), "r"(a[2]), "r"(a[3]), "r"(b[0]), "r"(b[1]));
}

// ---------------- prep: row-norm + A split (bf16 hi/lo) ----------------
__global__ void norm_splitA_kernel(const float* __restrict__ x){
    __shared__ float red[256];
    const int p = blockIdx.x, tid = threadIdx.x;
    const float* xr = x + (size_t)p * DDIM;
    float ss = 0.f;
    #pragma unroll
    for (int i = 0; i < 4; i++){ float v = xr[tid + i*256]; ss += v*v; }
    red[tid] = ss; __syncthreads();
    for (int o = 128; o > 0; o >>= 1){ if (tid < o) red[tid] += red[tid+o]; __syncthreads(); }
    float rn = 1.0f / fmaxf(sqrtf(red[0]), 1e-7f);
    #pragma unroll
    for (int i = 0; i < 4; i++){
        int d = tid + i*256;
        float v = xr[d] * rn;
        __nv_bfloat16 h = __float2bfloat16(v);
        g_Ah[(size_t)p*DDIM + d] = h;
        g_Al[(size_t)p*DDIM + d] = __float2bfloat16(v - __bfloat162float(h));
    }
}
__global__ void splitB_kernel(const float* __restrict__ W){
    size_t i = (size_t)blockIdx.x * 256 + threadIdx.x;
    float v = W[i];
    __nv_bfloat16 h = __float2bfloat16(v);
    g_Bh[i] = h;
    g_Bl[i] = __float2bfloat16(v - __bfloat162float(h));
}
__global__ void zerocs_kernel(){
    g_cs[blockIdx.x * 256 + threadIdx.x] = 0.f;
}
__global__ void ucalc_kernel(){
    int g = blockIdx.x * 256 + threadIdx.x;
    g_u[g] = 1.0f / (g_cs[g] + 1e-8f);
}

// ---------------- GEMM: logits = A_n @ W^T via mma.sync bf16, 2-term split ----------------
// CTA tile 128x128, K-chunk 64 (128B smem rows + 16B-XOR swizzle), 3-stage cp.async pipeline,
// single __syncthreads per chunk. Epilogue: store logits + fused per-column exp-sums
// (2 deterministic atomicAdd contributions per (b,k) cell).
#define GEMM_SMEM (3*65536)   // 3 stages * 4 tiles * 16KB

__device__ __forceinline__ void load_stage(uint32_t sm_stage,
                                           const __nv_bfloat16* const* gsrc,
                                           int ckk, int tid){
    #pragma unroll
    for (int t = 0; t < 4; t++){
        const char* src = (const char*)(gsrc[t] + ckk * 64);
        uint32_t dT = sm_stage + t * 16384;
        #pragma unroll
        for (int i = 0; i < 4; i++){
            int q = i * 256 + tid;        // 0..1023 : 16B chunk id
            int r = q >> 3, c = q & 7;
            const void* s = src + (size_t)r * (DDIM*2) + c * 16;
            uint32_t d = dT + (uint32_t)(r * 128) + (uint32_t)((c ^ (r & 7)) << 4);
            cp16(d, s);
        }
    }
    cp_commit();
}

__global__ void __launch_bounds__(256, 1) gemm_kernel(float* __restrict__ C){
    extern __shared__ char smem[];
    const uint32_t sb = s2u(smem);
    const int tid = threadIdx.x;
    const int wid = tid >> 5, lane = tid & 31;
    const int wm = wid >> 2;            // 0..1
    const int wn = wid & 3;             // 0..3
    const int m0 = blockIdx.y * 128;
    const int n0 = blockIdx.x * 128;

    const __nv_bfloat16* gsrc[4] = {
        g_Ah + (size_t)m0 * DDIM, g_Al + (size_t)m0 * DDIM,
        g_Bh + (size_t)n0 * DDIM, g_Bl + (size_t)n0 * DDIM };

    float acc[4][4][4];
    #pragma unroll
    for (int a = 0; a < 4; a++)
        #pragma unroll
        for (int b = 0; b < 4; b++)
            #pragma unroll
            for (int c = 0; c < 4; c++) acc[a][b][c] = 0.f;

    const int aRow = wm * 64 + (lane & 15);          // + mi*16
    const int aHalf = lane >> 4;
    const int l15 = lane & 15;
    const int bRow = wn * 32 + (l15 & 7);            // + ni*8
    const int bHalf = (l15 >> 3) & 1;

    load_stage(sb,         gsrc, 0, tid);
    load_stage(sb + 65536, gsrc, 1, tid);

    for (int ck = 0; ck < 16; ck++){
        cp_wait<1>();                   // my groups up to chunk ck complete
        __syncthreads();                // publish cp data + protect buffer reuse
        if (ck + 2 < 16)
            load_stage(sb + (uint32_t)(((ck + 2) % 3) * 65536), gsrc, ck + 2, tid);
        else
            cp_commit();                // keep group arithmetic constant

        const uint32_t stage = sb + (uint32_t)((ck % 3) * 65536);
        const uint32_t sAh = stage, sAl = stage + 16384;
        const uint32_t sBh = stage + 32768, sBl = stage + 49152;

        #pragma unroll
        for (int kk = 0; kk < 4; kk++){
            uint32_t Ah4[4][4], Al4[4][4], Bh2[4][2], Bl2[4][2];
            #pragma unroll
            for (int mi = 0; mi < 4; mi++){
                int row = aRow + mi * 16;
                int ch  = kk * 2 + aHalf;
                uint32_t off = (uint32_t)(row * 128 + ((ch ^ (row & 7)) << 4));
                ldm_x4(Ah4[mi], sAh + off);
                ldm_x4(Al4[mi], sAl + off);
            }
            #pragma unroll
            for (int ni = 0; ni < 4; ni++){
                int row = bRow + ni * 8;
                int ch  = kk * 2 + bHalf;
                uint32_t off = (uint32_t)(row * 128 + ((ch ^ (row & 7)) << 4));
                ldm_x2(Bh2[ni], sBh + off);
                ldm_x2(Bl2[ni], sBl + off);
            }
            #pragma unroll
            for (int mi = 0; mi < 4; mi++)
                #pragma unroll
                for (int ni = 0; ni < 4; ni++){
                    mma16816(acc[mi][ni], Ah4[mi], Bh2[ni]);
                    mma16816(acc[mi][ni], Ah4[mi], Bl2[ni]);
                    mma16816(acc[mi][ni], Al4[mi], Bh2[ni]);
                }
        }
    }

    // ---- epilogue 1: write fp32 logits ----
    float* Cp = C + (size_t)(m0 + wm * 64) * KCL + n0 + wn * 32;
    const int rr = lane >> 2, cc = (lane & 3) * 2;
    #pragma unroll
    for (int mi = 0; mi < 4; mi++)
        #pragma unroll
        for (int ni = 0; ni < 4; ni++){
            float* p0 = Cp + (size_t)(mi * 16 + rr) * KCL + ni * 8 + cc;
            float* p1 = p0 + (size_t)8 * KCL;
            *reinterpret_cast<float2*>(p0) = make_float2(acc[mi][ni][0], acc[mi][ni][1]);
            *reinterpret_cast<float2*>(p1) = make_float2(acc[mi][ni][2], acc[mi][ni][3]);
        }

    // ---- epilogue 2: fused column exp-sums (first Sinkhorn col pass) ----
    float csum[8];
    #pragma unroll
    for (int i = 0; i < 8; i++) csum[i] = 0.f;
    #pragma unroll
    for (int mi = 0; mi < 4; mi++)
        #pragma unroll
        for (int ni = 0; ni < 4; ni++){
            csum[ni*2+0] += expf(acc[mi][ni][0]*INV_T - SHIFT) + expf(acc[mi][ni][2]*INV_T - SHIFT);
            csum[ni*2+1] += expf(acc[mi][ni][1]*INV_T - SHIFT) + expf(acc[mi][ni][3]*INV_T - SHIFT);
        }
    // reduce over rr (lanes stride 4): lanes 0..3 end with warp totals (64 rows)
    #pragma unroll
    for (int o = 16; o >= 4; o >>= 1)
        #pragma unroll
        for (int i = 0; i < 8; i++) csum[i] += __shfl_down_sync(0xffffffffu, csum[i], o);

    __syncthreads();                    // smem free for reuse (pipeline fully drained)
    float* cs = reinterpret_cast<float*>(smem);   // [8 warps][32 cols]
    if (lane < 4){
        #pragma unroll
        for (int ni = 0; ni < 4; ni++){
            cs[wid*32 + ni*8 + lane*2 + 0] = csum[ni*2+0];
            cs[wid*32 + ni*8 + lane*2 + 1] = csum[ni*2+1];
        }
    }
    __syncthreads();
    if (wm == 0){                       // wid 0..3 combine wm pairs -> 1 atomic per column
        float vsum = cs[wid*32 + lane] + cs[(wid+4)*32 + lane];
        int b = blockIdx.y >> 1;        // batch of this M-tile
        atomicAdd(&g_cs[b*KCL + n0 + wn*32 + lane], vsum);   // 2 contributions/cell total
    }
}

// ---------------- Sinkhorn passes ----------------
// weighted col pass: t = sum_s E*v[s]; u <- u/(u*t+eps)
__global__ void colw_kernel(const float* __restrict__ L){
    int g = blockIdx.x * 256 + threadIdx.x;
    int b = g >> 13, k = g & (KCL - 1);
    const float* p = L + (size_t)b * SBATCH * KCL + k;
    const float* vv = g_v + b * SBATCH;
    float t = 0.f;
    #pragma unroll 8
    for (int s = 0; s < SBATCH; s++)
        t += expf(p[(size_t)s * KCL] * INV_T - SHIFT) * vv[s];
    float uo = g_u[g];
    g_u[g] = uo / (uo * t + 1e-8f);
}
// row pass: t = sum_k E*u[k]; v <- v/(v*t+eps). Optionally lse(logits/0.12).
__global__ void row_kernel(const float* __restrict__ L, int first, int computeLse){
    const int p = blockIdx.x, tid = threadIdx.x;
    const int b = p >> 8;
    const float* row = L + (size_t)p * KCL;
    const float* uu = g_u + (size_t)b * KCL;
    float t = 0.f, pm = -3.4e38f, ps = 0.f;
    for (int k = tid; k < KCL; k += 256){
        float l = row[k];
        t += expf(l * INV_T - SHIFT) * uu[k];
        if (computeLse){
            float q = l * INV_TP;
            float nm = fmaxf(pm, q);
            ps = ps * expf(pm - nm) + expf(q - nm);
            pm = nm;
        }
    }
    __shared__ float st[256], sm[256], ss[256];
    st[tid] = t; sm[tid] = pm; ss[tid] = ps; __syncthreads();
    for (int o = 128; o > 0; o >>= 1){
        if (tid < o){
            st[tid] += st[tid + o];
            float m1 = sm[tid], m2 = sm[tid + o];
            float nm = fmaxf(m1, m2);
            ss[tid] = ss[tid] * expf(m1 - nm) + ss[tid + o] * expf(m2 - nm);
            sm[tid] = nm;
        }
        __syncthreads();
    }
    if (tid == 0){
        float vo = first ? 1.0f : g_v[p];
        g_v[p] = vo / (vo * st[0] + 1e-8f);
        if (computeLse) g_lse[p] = sm[0] + logf(ss[0]);
    }
}
// fused row pass 3 + final: row in registers; v3; write assignments + row loss
__global__ void __launch_bounds__(256) rowfinal_kernel(float* __restrict__ L){
    const int p = blockIdx.x, tid = threadIdx.x;
    const int b = p >> 8;
    float4* row4 = reinterpret_cast<float4*>(L + (size_t)p * KCL);
    const float4* u4 = reinterpret_cast<const float4*>(g_u + (size_t)b * KCL);

    float4 lv[8];
    #pragma unroll
    for (int j = 0; j < 8; j++) lv[j] = row4[tid + j*256];

    float t = 0.f;
    #pragma unroll
    for (int j = 0; j < 8; j++){
        float4 uu = u4[tid + j*256];
        t += expf(lv[j].x * INV_T - SHIFT) * uu.x
           + expf(lv[j].y * INV_T - SHIFT) * uu.y
           + expf(lv[j].z * INV_T - SHIFT) * uu.z
           + expf(lv[j].w * INV_T - SHIFT) * uu.w;
    }
    __shared__ float red[256];
    __shared__ float vsh;
    red[tid] = t; __syncthreads();
    for (int o = 128; o > 0; o >>= 1){ if (tid < o) red[tid] += red[tid+o]; __syncthreads(); }
    if (tid == 0){
        float vo = g_v[p];
        vsh = vo / (vo * red[0] + 1e-8f);
    }
    __syncthreads();
    const float v = vsh, lse = g_lse[p];

    float acc = 0.f;
    #pragma unroll
    for (int j = 0; j < 8; j++){
        float4 uu = u4[tid + j*256];
        float4 a;
        a.x = expf(lv[j].x * INV_T - SHIFT) * uu.x * v;
        a.y = expf(lv[j].y * INV_T - SHIFT) * uu.y * v;
        a.z = expf(lv[j].z * INV_T - SHIFT) * uu.z * v;
        a.w = expf(lv[j].w * INV_T - SHIFT) * uu.w * v;
        acc += a.x * (lv[j].x * INV_TP - lse)
             + a.y * (lv[j].y * INV_TP - lse)
             + a.z * (lv[j].z * INV_TP - lse)
             + a.w * (lv[j].w * INV_TP - lse);
        row4[tid + j*256] = a;
    }
    __syncthreads();
    red[tid] = acc; __syncthreads();
    for (int o = 128; o > 0; o >>= 1){ if (tid < o) red[tid] += red[tid+o]; __syncthreads(); }
    if (tid == 0) g_rowloss[p] = red[0];
}
__global__ void loss_kernel(float* __restrict__ out, int idx){
    __shared__ float red[256];
    const int tid = threadIdx.x;
    float s = 0.f;
    for (int i = tid; i < NPOS; i += 256) s += g_rowloss[i];
    red[tid] = s; __syncthreads();
    for (int o = 128; o > 0; o >>= 1){ if (tid < o) red[tid] += red[tid+o]; __syncthreads(); }
    if (tid == 0) out[idx] = -red[0] * (1.0f / (float)NPOS);
}

// ---------------- launch ----------------
extern "C" void kernel_launch(void* const* d_in, const int* in_sizes, int n_in,
                              void* d_out, int out_size){
    (void)in_sizes; (void)n_in;
    const float* x = (const float*)d_in[0];   // [32,256,1024]
    const float* W = (const float*)d_in[1];   // [8192,1024]
    float* out = (float*)d_out;               // assignments [8192,8192] (+ loss at end)

    cudaFuncSetAttribute(gemm_kernel, cudaFuncAttributeMaxDynamicSharedMemorySize, GEMM_SMEM);

    norm_splitA_kernel<<<NPOS, 256>>>(x);
    splitB_kernel<<<(KCL * DDIM) / 256, 256>>>(W);
    zerocs_kernel<<<(NBATCH * KCL) / 256, 256>>>();
    gemm_kernel<<<dim3(KCL / 128, NPOS / 128), 256, GEMM_SMEM>>>(out);  // logits + col sums

    const int colBlocks = (NBATCH * KCL) / 256;   // 1024
    ucalc_kernel<<<colBlocks, 256>>>();           // iter1 col: u1 = 1/(cs+eps)
    row_kernel <<<NPOS, 256>>>(out, 1, 1);        // iter1 row: v1 (+ lse)
    colw_kernel<<<colBlocks, 256>>>(out);         // iter2 col: u2
    row_kernel <<<NPOS, 256>>>(out, 0, 0);        // iter2 row: v2
    colw_kernel<<<colBlocks, 256>>>(out);         // iter3 col: u3
    rowfinal_kernel<<<NPOS, 256>>>(out);          // iter3 row + assignments + row loss

    if (out_size > NPOS * KCL)
        loss_kernel<<<1, 256>>>(out, out_size - 1);
}

// round 8
// speedup vs baseline: 1.1733x; 1.0130x over previous
#include <cuda_runtime.h>
#include <cuda_bf16.h>
#include <cstdint>

// ---------------- problem constants ----------------
#define NPOS   8192      // B*S positions
#define KCL    8192      // clusters
#define DDIM   1024      // feature dim
#define SBATCH 256       // S
#define NBATCH 32        // B
#define INV_T  (1.0f/0.07f)
#define INV_TP (1.0f/0.12f)
#define SHIFT  30.0f     // constant exp shift (column-constant => cancels in Sinkhorn)

// ---------------- scratch (device globals; no allocation allowed) ----------------
__device__ __align__(256) __nv_bfloat16 g_Ah[NPOS*DDIM];
__device__ __align__(256) __nv_bfloat16 g_Al[NPOS*DDIM];
__device__ __align__(256) __nv_bfloat16 g_Bh[KCL*DDIM];
__device__ __align__(256) __nv_bfloat16 g_Bl[KCL*DDIM];
__device__ float g_cs[NBATCH*KCL];     // column sums (from GEMM epilogue)
__device__ float g_u [NBATCH*KCL];     // column scalers
__device__ float g_v [NPOS];           // row scalers
__device__ float g_lse[NPOS];          // logsumexp(logits/0.12) per row
__device__ float g_rowloss[NPOS];

// ---------------- helpers ----------------
__device__ __forceinline__ uint32_t s2u(const void* p){
    uint32_t a;
    asm("{ .reg .u64 t; cvta.to.shared.u64 t, %1; cvt.u32.u64 %0, t; }":"=r"(a):"l"(p));
    return a;
}
__device__ __forceinline__ void cp16(uint32_t dst, const void* src){
    asm volatile("cp.async.cg.shared.global [%0], [%1], 16;" :: "r"(dst), "l"(src) : "memory");
}
__device__ __forceinline__ void cp_commit(){
    asm volatile("cp.async.commit_group;" ::: "memory");
}
template<int N> __device__ __forceinline__ void cp_wait(){
    asm volatile("cp.async.wait_group %0;" :: "n"(N) : "memory");
}
__device__ __forceinline__ void ldm_x4(uint32_t* r, uint32_t addr){
    asm volatile("ldmatrix.sync.aligned.m8n8.x4.shared.b16 {%0,%1,%2,%3}, [%4];"
                 : "=r"(r[0]), "=r"(r[1]), "=r"(r[2]), "=r"(r[3]) : "r"(addr));
}
__device__ __forceinline__ void ldm_x2(uint32_t* r, uint32_t addr){
    asm volatile("ldmatrix.sync.aligned.m8n8.x2.shared.b16 {%0,%1}, [%2];"
                 : "=r"(r[0]), "=r"(r[1]) : "r"(addr));
}
__device__ __forceinline__ void mma16816(float* c, const uint32_t* a, const uint32_t* b){
    asm volatile("mma.sync.aligned.m16n8k16.row.col.f32.bf16.bf16.f32 "
                 "{%0,%1,%2,%3}, {%4,%5,%6,%7}, {%8,%9}, {%0,%1,%2,%3};"
                 : "+f"(c[0]), "+f"(c[1]), "+f"(c[2]), "+f"(c[3])
                 : "r"(a[0]), "r"(a[1]), "r"(a[2]), "r"(a[3]), "r"(b[0]), "r"(b[1]));
}

// ---------------- prep: row-norm + A split (bf16 hi/lo) ----------------
__global__ void norm_splitA_kernel(const float* __restrict__ x){
    __shared__ float red[256];
    const int p = blockIdx.x, tid = threadIdx.x;
    const float* xr = x + (size_t)p * DDIM;
    float ss = 0.f;
    #pragma unroll
    for (int i = 0; i < 4; i++){ float v = xr[tid + i*256]; ss += v*v; }
    red[tid] = ss; __syncthreads();
    for (int o = 128; o > 0; o >>= 1){ if (tid < o) red[tid] += red[tid+o]; __syncthreads(); }
    float rn = 1.0f / fmaxf(sqrtf(red[0]), 1e-7f);
    #pragma unroll
    for (int i = 0; i < 4; i++){
        int d = tid + i*256;
        float v = xr[d] * rn;
        __nv_bfloat16 h = __float2bfloat16(v);
        g_Ah[(size_t)p*DDIM + d] = h;
        g_Al[(size_t)p*DDIM + d] = __float2bfloat16(v - __bfloat162float(h));
    }
}
__global__ void splitB_kernel(const float* __restrict__ W){
    size_t i = (size_t)blockIdx.x * 256 + threadIdx.x;
    float v = W[i];
    __nv_bfloat16 h = __float2bfloat16(v);
    g_Bh[i] = h;
    g_Bl[i] = __float2bfloat16(v - __bfloat162float(h));
}
__global__ void zerocs_kernel(){
    g_cs[blockIdx.x * 256 + threadIdx.x] = 0.f;
}
__global__ void ucalc_kernel(){
    int g = blockIdx.x * 256 + threadIdx.x;
    g_u[g] = 1.0f / (g_cs[g] + 1e-8f);
}

// ---------------- GEMM: logits = A_n @ W^T via mma.sync bf16, 3-term split ----------------
// CTA tile 128x128, K-chunk 32 (64B smem rows, XOR-(row>>1)&3 swizzle), 3-stage cp.async
// pipeline, 2 CTAs/SM (96KB smem, <=128 regs). Epilogue: logits + fused column exp-sums.
#define GEMM_SMEM (3*32768)   // 3 stages * 4 tiles * 8KB

__device__ __forceinline__ void load_stage(uint32_t sm_stage,
                                           const __nv_bfloat16* const* gsrc,
                                           int ckk, int tid){
    #pragma unroll
    for (int t = 0; t < 4; t++){
        const char* src = (const char*)(gsrc[t] + ckk * 32);
        uint32_t dT = sm_stage + t * 8192;
        #pragma unroll
        for (int i = 0; i < 2; i++){
            int q = i * 256 + tid;        // 0..511 : 16B chunk id within tile
            int r = q >> 2, c = q & 3;
            const void* s = src + (size_t)r * (DDIM*2) + c * 16;
            uint32_t d = dT + (uint32_t)(r * 64) + (uint32_t)((c ^ ((r >> 1) & 3)) << 4);
            cp16(d, s);
        }
    }
    cp_commit();
}

__global__ void __launch_bounds__(256, 2) gemm_kernel(float* __restrict__ C){
    extern __shared__ char smem[];
    const uint32_t sb = s2u(smem);
    const int tid = threadIdx.x;
    const int wid = tid >> 5, lane = tid & 31;
    const int wm = wid >> 2;            // 0..1
    const int wn = wid & 3;             // 0..3
    const int m0 = blockIdx.y * 128;
    const int n0 = blockIdx.x * 128;

    const __nv_bfloat16* gsrc[4] = {
        g_Ah + (size_t)m0 * DDIM, g_Al + (size_t)m0 * DDIM,
        g_Bh + (size_t)n0 * DDIM, g_Bl + (size_t)n0 * DDIM };

    float acc[4][4][4];
    #pragma unroll
    for (int a = 0; a < 4; a++)
        #pragma unroll
        for (int b = 0; b < 4; b++)
            #pragma unroll
            for (int c = 0; c < 4; c++) acc[a][b][c] = 0.f;

    const int aRowB = wm * 64 + (lane & 15);         // + mi*16
    const int aHalf = lane >> 4;                     // 16B chunk within kk
    const int l15 = lane & 15;
    const int bRowB = wn * 32 + (l15 & 7);           // + ni*8
    const int bHalf = (l15 >> 3) & 1;

    load_stage(sb,         gsrc, 0, tid);
    load_stage(sb + 32768, gsrc, 1, tid);

    for (int ck = 0; ck < 32; ck++){
        cp_wait<1>();                   // chunk ck's group complete
        __syncthreads();                // publish cp data + protect buffer reuse
        if (ck + 2 < 32)
            load_stage(sb + (uint32_t)(((ck + 2) % 3) * 32768), gsrc, ck + 2, tid);
        else
            cp_commit();                // keep group accounting constant

        const uint32_t stage = sb + (uint32_t)((ck % 3) * 32768);
        const uint32_t sAh = stage, sAl = stage + 8192;
        const uint32_t sBh = stage + 16384, sBl = stage + 24576;

        #pragma unroll
        for (int kk = 0; kk < 2; kk++){
            // B frags for this k16 step
            uint32_t Bh2[4][2], Bl2[4][2];
            #pragma unroll
            for (int ni = 0; ni < 4; ni++){
                int row = bRowB + ni * 8;
                int ch  = kk * 2 + bHalf;
                uint32_t off = (uint32_t)(row * 64 + (((ch ^ ((row >> 1) & 3))) << 4));
                ldm_x2(Bh2[ni], sBh + off);
                ldm_x2(Bl2[ni], sBl + off);
            }
            // hh + hl terms: stream Ah one mi at a time (low register pressure)
            #pragma unroll
            for (int mi = 0; mi < 4; mi++){
                int row = aRowB + mi * 16;
                int ch  = kk * 2 + aHalf;
                uint32_t off = (uint32_t)(row * 64 + (((ch ^ ((row >> 1) & 3))) << 4));
                uint32_t Ah4[4];
                ldm_x4(Ah4, sAh + off);
                #pragma unroll
                for (int ni = 0; ni < 4; ni++){
                    mma16816(acc[mi][ni], Ah4, Bh2[ni]);
                    mma16816(acc[mi][ni], Ah4, Bl2[ni]);
                }
            }
            // lh term: stream Al one mi at a time
            #pragma unroll
            for (int mi = 0; mi < 4; mi++){
                int row = aRowB + mi * 16;
                int ch  = kk * 2 + aHalf;
                uint32_t off = (uint32_t)(row * 64 + (((ch ^ ((row >> 1) & 3))) << 4));
                uint32_t Al4[4];
                ldm_x4(Al4, sAl + off);
                #pragma unroll
                for (int ni = 0; ni < 4; ni++)
                    mma16816(acc[mi][ni], Al4, Bh2[ni]);
            }
        }
    }

    // ---- epilogue 1: write fp32 logits ----
    float* Cp = C + (size_t)(m0 + wm * 64) * KCL + n0 + wn * 32;
    const int rr = lane >> 2, cc = (lane & 3) * 2;
    #pragma unroll
    for (int mi = 0; mi < 4; mi++)
        #pragma unroll
        for (int ni = 0; ni < 4; ni++){
            float* p0 = Cp + (size_t)(mi * 16 + rr) * KCL + ni * 8 + cc;
            float* p1 = p0 + (size_t)8 * KCL;
            *reinterpret_cast<float2*>(p0) = make_float2(acc[mi][ni][0], acc[mi][ni][1]);
            *reinterpret_cast<float2*>(p1) = make_float2(acc[mi][ni][2], acc[mi][ni][3]);
        }

    // ---- epilogue 2: fused column exp-sums (first Sinkhorn col pass) ----
    float csum[8];
    #pragma unroll
    for (int i = 0; i < 8; i++) csum[i] = 0.f;
    #pragma unroll
    for (int mi = 0; mi < 4; mi++)
        #pragma unroll
        for (int ni = 0; ni < 4; ni++){
            csum[ni*2+0] += expf(acc[mi][ni][0]*INV_T - SHIFT) + expf(acc[mi][ni][2]*INV_T - SHIFT);
            csum[ni*2+1] += expf(acc[mi][ni][1]*INV_T - SHIFT) + expf(acc[mi][ni][3]*INV_T - SHIFT);
        }
    #pragma unroll
    for (int o = 16; o >= 4; o >>= 1)
        #pragma unroll
        for (int i = 0; i < 8; i++) csum[i] += __shfl_down_sync(0xffffffffu, csum[i], o);

    __syncthreads();                    // pipeline drained; smem reusable
    float* cs = reinterpret_cast<float*>(smem);   // [8 warps][32 cols]
    if (lane < 4){
        #pragma unroll
        for (int ni = 0; ni < 4; ni++){
            cs[wid*32 + ni*8 + lane*2 + 0] = csum[ni*2+0];
            cs[wid*32 + ni*8 + lane*2 + 1] = csum[ni*2+1];
        }
    }
    __syncthreads();
    if (wm == 0){                       // wid 0..3 combine wm pairs -> 1 atomic per column
        float vsum = cs[wid*32 + lane] + cs[(wid+4)*32 + lane];
        int b = blockIdx.y >> 1;        // batch of this M-tile
        atomicAdd(&g_cs[b*KCL + n0 + wn*32 + lane], vsum);   // 2 contributions/cell total
    }
}

// ---------------- Sinkhorn passes ----------------
__global__ void colw_kernel(const float* __restrict__ L){
    int g = blockIdx.x * 256 + threadIdx.x;
    int b = g >> 13, k = g & (KCL - 1);
    const float* p = L + (size_t)b * SBATCH * KCL + k;
    const float* vv = g_v + b * SBATCH;
    float t = 0.f;
    #pragma unroll 8
    for (int s = 0; s < SBATCH; s++)
        t += expf(p[(size_t)s * KCL] * INV_T - SHIFT) * vv[s];
    float uo = g_u[g];
    g_u[g] = uo / (uo * t + 1e-8f);
}
__global__ void row_kernel(const float* __restrict__ L, int first, int computeLse){
    const int p = blockIdx.x, tid = threadIdx.x;
    const int b = p >> 8;
    const float* row = L + (size_t)p * KCL;
    const float* uu = g_u + (size_t)b * KCL;
    float t = 0.f, pm = -3.4e38f, ps = 0.f;
    for (int k = tid; k < KCL; k += 256){
        float l = row[k];
        t += expf(l * INV_T - SHIFT) * uu[k];
        if (computeLse){
            float q = l * INV_TP;
            float nm = fmaxf(pm, q);
            ps = ps * expf(pm - nm) + expf(q - nm);
            pm = nm;
        }
    }
    __shared__ float st[256], sm[256], ss[256];
    st[tid] = t; sm[tid] = pm; ss[tid] = ps; __syncthreads();
    for (int o = 128; o > 0; o >>= 1){
        if (tid < o){
            st[tid] += st[tid + o];
            float m1 = sm[tid], m2 = sm[tid + o];
            float nm = fmaxf(m1, m2);
            ss[tid] = ss[tid] * expf(m1 - nm) + ss[tid + o] * expf(m2 - nm);
            sm[tid] = nm;
        }
        __syncthreads();
    }
    if (tid == 0){
        float vo = first ? 1.0f : g_v[p];
        g_v[p] = vo / (vo * st[0] + 1e-8f);
        if (computeLse) g_lse[p] = sm[0] + logf(ss[0]);
    }
}
// fused row pass 3 + final: row in registers; v3; write assignments + row loss
__global__ void __launch_bounds__(256) rowfinal_kernel(float* __restrict__ L){
    const int p = blockIdx.x, tid = threadIdx.x;
    const int b = p >> 8;
    float4* row4 = reinterpret_cast<float4*>(L + (size_t)p * KCL);
    const float4* u4 = reinterpret_cast<const float4*>(g_u + (size_t)b * KCL);

    float4 lv[8];
    #pragma unroll
    for (int j = 0; j < 8; j++) lv[j] = row4[tid + j*256];

    float t = 0.f;
    #pragma unroll
    for (int j = 0; j < 8; j++){
        float4 uu = u4[tid + j*256];
        t += expf(lv[j].x * INV_T - SHIFT) * uu.x
           + expf(lv[j].y * INV_T - SHIFT) * uu.y
           + expf(lv[j].z * INV_T - SHIFT) * uu.z
           + expf(lv[j].w * INV_T - SHIFT) * uu.w;
    }
    __shared__ float red[256];
    __shared__ float vsh;
    red[tid] = t; __syncthreads();
    for (int o = 128; o > 0; o >>= 1){ if (tid < o) red[tid] += red[tid+o]; __syncthreads(); }
    if (tid == 0){
        float vo = g_v[p];
        vsh = vo / (vo * red[0] + 1e-8f);
    }
    __syncthreads();
    const float v = vsh, lse = g_lse[p];

    float acc = 0.f;
    #pragma unroll
    for (int j = 0; j < 8; j++){
        float4 uu = u4[tid + j*256];
        float4 a;
        a.x = expf(lv[j].x * INV_T - SHIFT) * uu.x * v;
        a.y = expf(lv[j].y * INV_T - SHIFT) * uu.y * v;
        a.z = expf(lv[j].z * INV_T - SHIFT) * uu.z * v;
        a.w = expf(lv[j].w * INV_T - SHIFT) * uu.w * v;
        acc += a.x * (lv[j].x * INV_TP - lse)
             + a.y * (lv[j].y * INV_TP - lse)
             + a.z * (lv[j].z * INV_TP - lse)
             + a.w * (lv[j].w * INV_TP - lse);
        row4[tid + j*256] = a;
    }
    __syncthreads();
    red[tid] = acc; __syncthreads();
    for (int o = 128; o > 0; o >>= 1){ if (tid < o) red[tid] += red[tid+o]; __syncthreads(); }
    if (tid == 0) g_rowloss[p] = red[0];
}
__global__ void loss_kernel(float* __restrict__ out, int idx){
    __shared__ float red[256];
    const int tid = threadIdx.x;
    float s = 0.f;
    for (int i = tid; i < NPOS; i += 256) s += g_rowloss[i];
    red[tid] = s; __syncthreads();
    for (int o = 128; o > 0; o >>= 1){ if (tid < o) red[tid] += red[tid+o]; __syncthreads(); }
    if (tid == 0) out[idx] = -red[0] * (1.0f / (float)NPOS);
}

// ---------------- launch ----------------
extern "C" void kernel_launch(void* const* d_in, const int* in_sizes, int n_in,
                              void* d_out, int out_size){
    (void)in_sizes; (void)n_in;
    const float* x = (const float*)d_in[0];   // [32,256,1024]
    const float* W = (const float*)d_in[1];   // [8192,1024]
    float* out = (float*)d_out;               // assignments [8192,8192] (+ loss at end)

    cudaFuncSetAttribute(gemm_kernel, cudaFuncAttributeMaxDynamicSharedMemorySize, GEMM_SMEM);

    norm_splitA_kernel<<<NPOS, 256>>>(x);
    splitB_kernel<<<(KCL * DDIM) / 256, 256>>>(W);
    zerocs_kernel<<<(NBATCH * KCL) / 256, 256>>>();
    gemm_kernel<<<dim3(KCL / 128, NPOS / 128), 256, GEMM_SMEM>>>(out);  // logits + col sums

    const int colBlocks = (NBATCH * KCL) / 256;   // 1024
    ucalc_kernel<<<colBlocks, 256>>>();           // iter1 col: u1 = 1/(cs+eps)
    row_kernel <<<NPOS, 256>>>(out, 1, 1);        // iter1 row: v1 (+ lse)
    colw_kernel<<<colBlocks, 256>>>(out);         // iter2 col: u2
    row_kernel <<<NPOS, 256>>>(out, 0, 0);        // iter2 row: v2
    colw_kernel<<<colBlocks, 256>>>(out);         // iter3 col: u3
    rowfinal_kernel<<<NPOS, 256>>>(out);          // iter3 row + assignments + row loss

    if (out_size > NPOS * KCL)
        loss_kernel<<<1, 256>>>(out, out_size - 1);
}